// round 9
// baseline (speedup 1.0000x reference)
#include <cuda_runtime.h>
#include <cuda_fp16.h>
#include <cstdint>

// ---------------- problem dims ----------------
#define M_DIM 4096
#define N_DIM 1024
#define E_DIM 16
#define I_DIM 1024
#define K_DIM 16384
#define KS    16448          // K extended by one BK tile carrying cw/bias rank-16 term

// ---------------- GEMM config -----------------
#define BM 128
#define BN 256
#define BK 64
#define STAGES 3
#define NTHREADS 256   // 8 warps, {Wm=2, Wn=4}, 64x64 warp tiles

// per-stage smem: A[128 m][64 k] fp16 16KB + B[64 k][256 n] fp16 32KB
#define A_OFF 0
#define B_OFF 16384
#define STAGE_BYTES 49152
#define BAR_BASE (STAGES * STAGE_BYTES)          // 147456
#define FULL_OFF(s)  (BAR_BASE + (s) * 8)
#define EMPTY_OFF(s) (BAR_BASE + 24 + (s) * 8)
#define SMEM_TOTAL (BAR_BASE + 64)               // 147520

// ---------------- device scratch --------------
__device__ __align__(1024) __half g_A[(size_t)M_DIM * KS];  // ~128.5 MiB: [cw*x | cw | 0]
__device__ __align__(1024) __half g_W[(size_t)KS * N_DIM];  // ~32.1 MiB:  [W ; bias ; 0]

// ---------------- fused prep (16B stores) ------------------
__global__ void prep_all_kernel(const float* __restrict__ x,
                                const float* __restrict__ cw,
                                const float* __restrict__ W,
                                const float* __restrict__ bias) {
    const size_t NW8 = (size_t)K_DIM * N_DIM / 8;        // 2097152 (8-elem units)
    const size_t NA8 = (size_t)M_DIM * K_DIM / 8;        // 8388608
    const size_t NTL = (size_t)M_DIM * 64 + 64 * N_DIM;  // 327680 scalar tail
    const size_t total = NW8 + NA8 + NTL;
    size_t idx    = (size_t)blockIdx.x * blockDim.x + threadIdx.x;
    size_t stride = (size_t)gridDim.x * blockDim.x;
    for (; idx < total; idx += stride) {
        if (idx < NW8) {
            size_t base = idx * 8;
            float4 w0 = *reinterpret_cast<const float4*>(W + base);
            float4 w1 = *reinterpret_cast<const float4*>(W + base + 4);
            uint4 o;
            o.x = __half2_raw(__floats2half2_rn(w0.x, w0.y)).x |
                  ((uint32_t)__half2_raw(__floats2half2_rn(w0.x, w0.y)).y << 16);
            // build via union to keep it simple
            __half2 h0 = __floats2half2_rn(w0.x, w0.y);
            __half2 h1 = __floats2half2_rn(w0.z, w0.w);
            __half2 h2 = __floats2half2_rn(w1.x, w1.y);
            __half2 h3 = __floats2half2_rn(w1.z, w1.w);
            o.x = *reinterpret_cast<uint32_t*>(&h0);
            o.y = *reinterpret_cast<uint32_t*>(&h1);
            o.z = *reinterpret_cast<uint32_t*>(&h2);
            o.w = *reinterpret_cast<uint32_t*>(&h3);
            *reinterpret_cast<uint4*>(g_W + base) = o;
        } else if (idx < NW8 + NA8) {
            size_t base = (idx - NW8) * 8;
            size_t b = base >> 14;
            int    k = (int)(base & 16383);
            float c = cw[b * E_DIM + (k >> 10)];   // 8-elem unit never crosses expert boundary
            float4 x0 = *reinterpret_cast<const float4*>(x + (b << 10) + (k & 1023));
            float4 x1 = *reinterpret_cast<const float4*>(x + (b << 10) + (k & 1023) + 4);
            __half2 h0 = __floats2half2_rn(c * x0.x, c * x0.y);
            __half2 h1 = __floats2half2_rn(c * x0.z, c * x0.w);
            __half2 h2 = __floats2half2_rn(c * x1.x, c * x1.y);
            __half2 h3 = __floats2half2_rn(c * x1.z, c * x1.w);
            uint4 o;
            o.x = *reinterpret_cast<uint32_t*>(&h0);
            o.y = *reinterpret_cast<uint32_t*>(&h1);
            o.z = *reinterpret_cast<uint32_t*>(&h2);
            o.w = *reinterpret_cast<uint32_t*>(&h3);
            *reinterpret_cast<uint4*>(g_A + b * KS + k) = o;
        } else {
            size_t j = idx - NW8 - NA8;
            if (j < (size_t)M_DIM * 64) {
                int b = (int)(j >> 6), e = (int)(j & 63);
                g_A[(size_t)b * KS + K_DIM + e] =
                    (e < E_DIM) ? __float2half_rn(cw[b * E_DIM + e]) : __half(0.f);
            } else {
                size_t t = j - (size_t)M_DIM * 64;
                int e = (int)(t >> 10), o = (int)(t & 1023);
                g_W[(size_t)(K_DIM + e) * N_DIM + o] =
                    (e < E_DIM) ? __float2half_rn(bias[e * N_DIM + o]) : __half(0.f);
            }
        }
    }
}

// ---------------- asm helpers ----------------
__device__ __forceinline__ void cp_async16(uint32_t s, const void* g) {
    asm volatile("cp.async.cg.shared.global [%0], [%1], 16;\n" :: "r"(s), "l"(g));
}
__device__ __forceinline__ void cpasync_arrive_noinc(uint32_t mbar) {
    asm volatile("cp.async.mbarrier.arrive.noinc.shared::cta.b64 [%0];" :: "r"(mbar) : "memory");
}
__device__ __forceinline__ void mbar_init(uint32_t a, uint32_t cnt) {
    asm volatile("mbarrier.init.shared.b64 [%0], %1;" :: "r"(a), "r"(cnt) : "memory");
}
__device__ __forceinline__ void mbar_arrive(uint32_t a) {
    asm volatile("mbarrier.arrive.shared.b64 _, [%0];" :: "r"(a) : "memory");
}
__device__ __forceinline__ void wait_parity(uint32_t mbar, uint32_t ph) {
    asm volatile("{\n\t.reg .pred P;\nWL%=:\n\t"
                 "mbarrier.try_wait.parity.acquire.cta.shared::cta.b64 P, [%0], %1, 0x989680;\n\t"
                 "@!P bra WL%=;\n\t}"
                 :: "r"(mbar), "r"(ph) : "memory");
}
__device__ __forceinline__ void ldsm_x4(uint32_t* r, uint32_t addr) {
    asm volatile("ldmatrix.sync.aligned.m8n8.x4.shared.b16 {%0,%1,%2,%3}, [%4];"
                 : "=r"(r[0]), "=r"(r[1]), "=r"(r[2]), "=r"(r[3]) : "r"(addr));
}
__device__ __forceinline__ void ldsm_x4_t(uint32_t* r, uint32_t addr) {
    asm volatile("ldmatrix.sync.aligned.m8n8.x4.trans.shared.b16 {%0,%1,%2,%3}, [%4];"
                 : "=r"(r[0]), "=r"(r[1]), "=r"(r[2]), "=r"(r[3]) : "r"(addr));
}
__device__ __forceinline__ void mma_f16(float* c, const uint32_t* a, const uint32_t* b) {
    asm volatile(
        "mma.sync.aligned.m16n8k16.row.col.f32.f16.f16.f32 "
        "{%0,%1,%2,%3}, {%4,%5,%6,%7}, {%8,%9}, {%0,%1,%2,%3};"
        : "+f"(c[0]), "+f"(c[1]), "+f"(c[2]), "+f"(c[3])
        : "r"(a[0]), "r"(a[1]), "r"(a[2]), "r"(a[3]), "r"(b[0]), "r"(b[1]));
}

// ---------------- tile loader ----------------
// A tile: [128 m][64 k], row = 128B = 8 chunks, swizzle ch ^ (row & 7)
//   thread t: row = t>>1, chunks (t&1)*4 .. +3
// B tile: [64 k][256 n], row = 512B = 32 chunks, swizzle ch ^ (r & 7)
//   thread t: row = t>>2, chunks (t&3)*8 .. +7
__device__ __forceinline__ void issue_stage(uint32_t st,
                                            const __half* pA, const __half* pB,
                                            int arow, int ac0, int brow, int bc0) {
    const uint32_t abase = st + A_OFF + (uint32_t)(arow * 128);
    const int axor = arow & 7;
#pragma unroll
    for (int p = 0; p < 4; ++p)
        cp_async16(abase + (((ac0 + p) ^ axor) << 4), pA + p * 8);
    const uint32_t bbase = st + B_OFF + (uint32_t)(brow * 512);
    const int bxor = brow & 7;
#pragma unroll
    for (int p = 0; p < 8; ++p)
        cp_async16(bbase + ((((bc0 + p) & 31) ^ bxor) << 4) + (((bc0 + p) >> 5) << 9),
                   pB + p * 8);
}

// ---------------- main GEMM (64x64 warp tiles, mbarrier ring) ----------------
__global__ void __launch_bounds__(NTHREADS, 1)
gemm_kernel(float* __restrict__ out) {
    extern __shared__ char smem_raw[];
    const uint32_t smem_base = (uint32_t)__cvta_generic_to_shared(smem_raw);
    const int tid  = threadIdx.x;
    const int lane = tid & 31;
    const int warp = tid >> 5;
    const int wm   = warp >> 2;   // 0..1
    const int wn   = warp & 3;    // 0..3
    const int bm0  = blockIdx.y * BM;
    const int bn0  = blockIdx.x * BN;

    if (tid == 0) {
#pragma unroll
        for (int s = 0; s < STAGES; ++s) {
            mbar_init(smem_base + FULL_OFF(s),  NTHREADS);
            mbar_init(smem_base + EMPTY_OFF(s), 8);
        }
    }
    __syncthreads();

    // producer mapping
    const int arow = tid >> 1, ac0 = (tid & 1) * 4;
    const int brow = tid >> 2, bc0 = (tid & 3) * 8;
    const __half* pA = g_A + (size_t)(bm0 + arow) * KS + ac0 * 8;
    const __half* pB = g_W + (size_t)brow * N_DIM + bn0 + bc0 * 8;

    float c[4][8][4];
#pragma unroll
    for (int i = 0; i < 4; ++i)
#pragma unroll
        for (int j = 0; j < 8; ++j)
#pragma unroll
            for (int k = 0; k < 4; ++k) c[i][j][k] = 0.f;

    const int KT = KS / BK;  // 257

#pragma unroll
    for (int s = 0; s < STAGES - 1; ++s) {
        issue_stage(smem_base + s * STAGE_BYTES, pA, pB, arow, ac0, brow, bc0);
        cpasync_arrive_noinc(smem_base + FULL_OFF(s));
        pA += BK; pB += (size_t)BK * N_DIM;
    }

    const int a_row16 = lane & 15;
    const int hi_half = lane >> 4;

    int prod_s = STAGES - 1; uint32_t prod_ph = 1;
    int cons_s = 0;          uint32_t cons_ph = 0;

    for (int kt = 0; kt < KT; ++kt) {
        if (kt + STAGES - 1 < KT) {
            wait_parity(smem_base + EMPTY_OFF(prod_s), prod_ph);
            issue_stage(smem_base + prod_s * STAGE_BYTES, pA, pB, arow, ac0, brow, bc0);
            cpasync_arrive_noinc(smem_base + FULL_OFF(prod_s));
            pA += BK; pB += (size_t)BK * N_DIM;
            if (++prod_s == STAGES) { prod_s = 0; prod_ph ^= 1; }
        }

        wait_parity(smem_base + FULL_OFF(cons_s), cons_ph);
        const uint32_t st = smem_base + cons_s * STAGE_BYTES;
#pragma unroll
        for (int s = 0; s < 4; ++s) {       // four k16 steps per BK=64
            uint32_t a[4][4];
#pragma unroll
            for (int mt = 0; mt < 4; ++mt) {
                int row = wm * 64 + mt * 16 + a_row16;
                int ch  = s * 2 + hi_half;
                uint32_t off = (uint32_t)(row * 128 + ((ch ^ (row & 7)) << 4));
                ldsm_x4(a[mt], st + A_OFF + off);
            }
            uint32_t b[8][2];
#pragma unroll
            for (int ntp = 0; ntp < 4; ++ntp) {
                int r  = s * 16 + (lane & 15);
                int ch = wn * 8 + ntp * 2 + hi_half;      // 0..31
                uint32_t off = (uint32_t)(r * 512 + ((ch ^ (r & 7)) << 4));
                uint32_t t[4];
                ldsm_x4_t(t, st + B_OFF + off);
                b[ntp * 2][0] = t[0];     b[ntp * 2][1] = t[1];
                b[ntp * 2 + 1][0] = t[2]; b[ntp * 2 + 1][1] = t[3];
            }
#pragma unroll
            for (int mt = 0; mt < 4; ++mt)
#pragma unroll
                for (int nt = 0; nt < 8; ++nt)
                    mma_f16(c[mt][nt], a[mt], b[nt]);
        }
        if (lane == 0) mbar_arrive(smem_base + EMPTY_OFF(cons_s));
        if (++cons_s == STAGES) { cons_s = 0; cons_ph ^= 1; }
    }

    // epilogue: ReLU + store (bias folded via K-extension)
    const int gr = lane >> 2;
    const int ct = lane & 3;
#pragma unroll
    for (int mt = 0; mt < 4; ++mt) {
#pragma unroll
        for (int nt = 0; nt < 8; ++nt) {
            int row = bm0 + wm * 64 + mt * 16 + gr;
            int o   = bn0 + wn * 64 + nt * 8 + ct * 2;
            size_t i0 = (size_t)row * N_DIM + o;
            out[i0]     = fmaxf(c[mt][nt][0], 0.f);
            out[i0 + 1] = fmaxf(c[mt][nt][1], 0.f);
            size_t i1 = i0 + (size_t)8 * N_DIM;
            out[i1]     = fmaxf(c[mt][nt][2], 0.f);
            out[i1 + 1] = fmaxf(c[mt][nt][3], 0.f);
        }
    }
}

// ---------------- launch -----------------------------------------------------
extern "C" void kernel_launch(void* const* d_in, const int* in_sizes, int n_in,
                              void* d_out, int out_size) {
    const float* x = nullptr;
    const float* cw = nullptr;
    const float* W = nullptr;
    const float* bias = nullptr;
    for (int i = 0; i < n_in; ++i) {
        switch (in_sizes[i]) {
            case M_DIM * I_DIM:         x    = (const float*)d_in[i]; break;
            case M_DIM * E_DIM:         cw   = (const float*)d_in[i]; break;
            case E_DIM * I_DIM * N_DIM: W    = (const float*)d_in[i]; break;
            case E_DIM * N_DIM:         bias = (const float*)d_in[i]; break;
            default: break;
        }
    }
    float* out = (float*)d_out;

    prep_all_kernel<<<8192, 256>>>(x, cw, W, bias);

    cudaFuncSetAttribute(gemm_kernel, cudaFuncAttributeMaxDynamicSharedMemorySize,
                         SMEM_TOTAL);
    dim3 grid(N_DIM / BN, M_DIM / BM);  // (4, 32) = 128 CTAs, single wave
    gemm_kernel<<<grid, NTHREADS, SMEM_TOTAL>>>(out);
}

// round 10
// speedup vs baseline: 1.5924x; 1.5924x over previous
#include <cuda_runtime.h>
#include <cuda_fp16.h>
#include <cstdint>

// ---------------- problem dims ----------------
#define M_DIM 4096
#define N_DIM 1024
#define E_DIM 16
#define I_DIM 1024
#define K_DIM 16384
#define KS    16448          // K extended by one BK tile carrying cw/bias rank-16 term

// ---------------- GEMM config -----------------
#define BM 128
#define BN 128
#define BK 64
#define STAGES 3
#define NTHREADS 256

// smem: 3 stages of (A 16KB + B 16KB), then mbarriers
#define A_OFF 0
#define B_OFF 16384
#define STAGE_BYTES 32768
#define BAR_BASE (STAGES * STAGE_BYTES)          // 98304
#define FULL_OFF(s)  (BAR_BASE + (s) * 8)
#define EMPTY_OFF(s) (BAR_BASE + 24 + (s) * 8)
#define SMEM_TOTAL (BAR_BASE + 64)               // 98368 -> 2 CTAs/SM

// ---------------- device scratch --------------
__device__ __align__(1024) __half g_A[(size_t)M_DIM * KS];  // ~128.5 MiB: [cw*x | cw | 0]
__device__ __align__(1024) __half g_W[(size_t)KS * N_DIM];  // ~32.1 MiB:  [W ; bias ; 0]

// ---------------- prep kernels ----------------
// W fp32 -> fp16, 8 elems / thread-iter, 16B stores
__global__ void prep_w_kernel(const float* __restrict__ W) {
    size_t idx    = (size_t)blockIdx.x * blockDim.x + threadIdx.x;
    size_t stride = (size_t)gridDim.x * blockDim.x;
    const size_t total8 = (size_t)K_DIM * N_DIM / 8;
    for (; idx < total8; idx += stride) {
        size_t base = idx * 8;
        float4 w0 = *reinterpret_cast<const float4*>(W + base);
        float4 w1 = *reinterpret_cast<const float4*>(W + base + 4);
        __half2 h0 = __floats2half2_rn(w0.x, w0.y);
        __half2 h1 = __floats2half2_rn(w0.z, w0.w);
        __half2 h2 = __floats2half2_rn(w1.x, w1.y);
        __half2 h3 = __floats2half2_rn(w1.z, w1.w);
        uint4 o;
        o.x = *reinterpret_cast<uint32_t*>(&h0);
        o.y = *reinterpret_cast<uint32_t*>(&h1);
        o.z = *reinterpret_cast<uint32_t*>(&h2);
        o.w = *reinterpret_cast<uint32_t*>(&h3);
        *reinterpret_cast<uint4*>(g_W + base) = o;
    }
}

// A prep, x read ONCE: thread -> (b, i4). Loads x[b][i4..i4+3] once, cw[b][0..15]
// (L1 broadcast across the 256 threads sharing b), writes 16 experts' 8B chunks.
__global__ void prep_a_kernel(const float* __restrict__ x,
                              const float* __restrict__ cw) {
    size_t idx    = (size_t)blockIdx.x * blockDim.x + threadIdx.x;
    size_t stride = (size_t)gridDim.x * blockDim.x;
    const size_t total = (size_t)M_DIM * (I_DIM / 4);     // 1,048,576
    for (; idx < total; idx += stride) {
        size_t b  = idx >> 8;            // / 256
        int    i4 = (int)(idx & 255) * 4;
        float4 xv = *reinterpret_cast<const float4*>(x + (b << 10) + i4);
        const float4 c0 = *reinterpret_cast<const float4*>(cw + b * E_DIM);
        const float4 c1 = *reinterpret_cast<const float4*>(cw + b * E_DIM + 4);
        const float4 c2 = *reinterpret_cast<const float4*>(cw + b * E_DIM + 8);
        const float4 c3 = *reinterpret_cast<const float4*>(cw + b * E_DIM + 12);
        float cs[16] = {c0.x, c0.y, c0.z, c0.w, c1.x, c1.y, c1.z, c1.w,
                        c2.x, c2.y, c2.z, c2.w, c3.x, c3.y, c3.z, c3.w};
        __half* dst = g_A + b * KS + i4;
#pragma unroll
        for (int e = 0; e < E_DIM; ++e) {
            float c = cs[e];
            __half2 h0 = __floats2half2_rn(c * xv.x, c * xv.y);
            __half2 h1 = __floats2half2_rn(c * xv.z, c * xv.w);
            uint2 o;
            o.x = *reinterpret_cast<uint32_t*>(&h0);
            o.y = *reinterpret_cast<uint32_t*>(&h1);
            *reinterpret_cast<uint2*>(dst + e * I_DIM) = o;
        }
    }
}

// Tail K-tile: A cols 16384..16447 = [cw | 0], W rows 16384..16447 = [bias ; 0]
__global__ void prep_tail_kernel(const float* __restrict__ cw,
                                 const float* __restrict__ bias) {
    int idx = blockIdx.x * blockDim.x + threadIdx.x;
    if (idx < M_DIM * 64) {
        int b = idx >> 6, e = idx & 63;
        g_A[(size_t)b * KS + K_DIM + e] =
            (e < E_DIM) ? __float2half_rn(cw[b * E_DIM + e]) : __half(0.f);
    } else {
        int j = idx - M_DIM * 64;
        if (j < 64 * N_DIM) {
            int e = j >> 10, o = j & 1023;
            g_W[(size_t)(K_DIM + e) * N_DIM + o] =
                (e < E_DIM) ? __float2half_rn(bias[e * N_DIM + o]) : __half(0.f);
        }
    }
}

// ---------------- asm helpers ----------------
__device__ __forceinline__ void cp_async16(uint32_t s, const void* g) {
    asm volatile("cp.async.cg.shared.global [%0], [%1], 16;\n" :: "r"(s), "l"(g));
}
__device__ __forceinline__ void cpasync_arrive_noinc(uint32_t mbar) {
    asm volatile("cp.async.mbarrier.arrive.noinc.shared::cta.b64 [%0];" :: "r"(mbar) : "memory");
}
__device__ __forceinline__ void mbar_init(uint32_t a, uint32_t cnt) {
    asm volatile("mbarrier.init.shared.b64 [%0], %1;" :: "r"(a), "r"(cnt) : "memory");
}
__device__ __forceinline__ void mbar_arrive(uint32_t a) {
    asm volatile("mbarrier.arrive.shared.b64 _, [%0];" :: "r"(a) : "memory");
}
__device__ __forceinline__ void wait_parity(uint32_t mbar, uint32_t ph) {
    asm volatile("{\n\t.reg .pred P;\nWL%=:\n\t"
                 "mbarrier.try_wait.parity.acquire.cta.shared::cta.b64 P, [%0], %1, 0x989680;\n\t"
                 "@!P bra WL%=;\n\t}"
                 :: "r"(mbar), "r"(ph) : "memory");
}
__device__ __forceinline__ void ldsm_x4(uint32_t* r, uint32_t addr) {
    asm volatile("ldmatrix.sync.aligned.m8n8.x4.shared.b16 {%0,%1,%2,%3}, [%4];"
                 : "=r"(r[0]), "=r"(r[1]), "=r"(r[2]), "=r"(r[3]) : "r"(addr));
}
__device__ __forceinline__ void ldsm_x4_t(uint32_t* r, uint32_t addr) {
    asm volatile("ldmatrix.sync.aligned.m8n8.x4.trans.shared.b16 {%0,%1,%2,%3}, [%4];"
                 : "=r"(r[0]), "=r"(r[1]), "=r"(r[2]), "=r"(r[3]) : "r"(addr));
}
__device__ __forceinline__ void mma_f16(float* c, const uint32_t* a, const uint32_t* b) {
    asm volatile(
        "mma.sync.aligned.m16n8k16.row.col.f32.f16.f16.f32 "
        "{%0,%1,%2,%3}, {%4,%5,%6,%7}, {%8,%9}, {%0,%1,%2,%3};"
        : "+f"(c[0]), "+f"(c[1]), "+f"(c[2]), "+f"(c[3])
        : "r"(a[0]), "r"(a[1]), "r"(a[2]), "r"(a[3]), "r"(b[0]), "r"(b[1]));
}

// ---------------- tile loader (R8 layout, unchanged) ----------------
__device__ __forceinline__ void issue_stage(uint32_t st,
                                            const __half* pA, const __half* pB,
                                            uint32_t dstA0, uint32_t dstB0) {
#pragma unroll
    for (int p = 0; p < 4; ++p)
        cp_async16(st + A_OFF + dstA0 + p * (32 * 128),
                   pA + (size_t)p * 32 * KS);
#pragma unroll
    for (int p = 0; p < 4; ++p)
        cp_async16(st + B_OFF + dstB0 + p * (16 * 256),
                   pB + (size_t)p * 16 * N_DIM);
}

// ---------------- main GEMM (R8 core, byte-identical mainloop) ---------------
__global__ void __launch_bounds__(NTHREADS, 2)
gemm_kernel(float* __restrict__ out) {
    extern __shared__ char smem_raw[];
    const uint32_t smem_base = (uint32_t)__cvta_generic_to_shared(smem_raw);
    const int tid  = threadIdx.x;
    const int lane = tid & 31;
    const int warp = tid >> 5;
    const int wm   = warp >> 2;   // 0..1
    const int wn   = warp & 3;    // 0..3
    const int bm0  = blockIdx.y * BM;
    const int bn0  = blockIdx.x * BN;

    if (tid == 0) {
#pragma unroll
        for (int s = 0; s < STAGES; ++s) {
            mbar_init(smem_base + FULL_OFF(s),  NTHREADS);
            mbar_init(smem_base + EMPTY_OFF(s), 8);
        }
    }
    __syncthreads();

    const int arow = tid >> 3, ach = tid & 7;
    const int brow = tid >> 4, bch = tid & 15;
    const uint32_t dstA0 = (uint32_t)(arow * 128 + ((ach ^ (arow & 7)) << 4));
    const uint32_t dstB0 = (uint32_t)(brow * 256 + ((bch ^ (brow & 7)) << 4));
    const __half* pA = g_A + (size_t)(bm0 + arow) * KS + ach * 8;
    const __half* pB = g_W + (size_t)brow * N_DIM + bn0 + bch * 8;

    float c[4][4][4];
#pragma unroll
    for (int i = 0; i < 4; ++i)
#pragma unroll
        for (int j = 0; j < 4; ++j)
#pragma unroll
            for (int k = 0; k < 4; ++k) c[i][j][k] = 0.f;

    const int KT = KS / BK;  // 257

#pragma unroll
    for (int s = 0; s < STAGES - 1; ++s) {
        issue_stage(smem_base + s * STAGE_BYTES, pA, pB, dstA0, dstB0);
        cpasync_arrive_noinc(smem_base + FULL_OFF(s));
        pA += BK; pB += (size_t)BK * N_DIM;
    }

    const int a_row16 = lane & 15;
    const int hi_half = lane >> 4;

    int prod_s = STAGES - 1; uint32_t prod_ph = 1;
    int cons_s = 0;          uint32_t cons_ph = 0;

    for (int kt = 0; kt < KT; ++kt) {
        if (kt + STAGES - 1 < KT) {
            wait_parity(smem_base + EMPTY_OFF(prod_s), prod_ph);
            issue_stage(smem_base + prod_s * STAGE_BYTES, pA, pB, dstA0, dstB0);
            cpasync_arrive_noinc(smem_base + FULL_OFF(prod_s));
            pA += BK; pB += (size_t)BK * N_DIM;
            if (++prod_s == STAGES) { prod_s = 0; prod_ph ^= 1; }
        }

        wait_parity(smem_base + FULL_OFF(cons_s), cons_ph);
        const uint32_t st = smem_base + cons_s * STAGE_BYTES;
#pragma unroll
        for (int s = 0; s < 4; ++s) {
            uint32_t a[4][4];
#pragma unroll
            for (int mt = 0; mt < 4; ++mt) {
                int row = wm * 64 + mt * 16 + a_row16;
                int ch  = s * 2 + hi_half;
                uint32_t off = (uint32_t)(row * 128 + ((ch ^ (row & 7)) << 4));
                ldsm_x4(a[mt], st + A_OFF + off);
            }
            uint32_t b[4][2];
#pragma unroll
            for (int nt2 = 0; nt2 < 2; ++nt2) {
                int r  = s * 16 + (lane & 15);
                int ch = wn * 4 + nt2 * 2 + hi_half;
                uint32_t off = (uint32_t)(r * 256 + ((ch ^ (r & 7)) << 4));
                uint32_t t[4];
                ldsm_x4_t(t, st + B_OFF + off);
                b[nt2 * 2][0] = t[0];     b[nt2 * 2][1] = t[1];
                b[nt2 * 2 + 1][0] = t[2]; b[nt2 * 2 + 1][1] = t[3];
            }
#pragma unroll
            for (int mt = 0; mt < 4; ++mt)
#pragma unroll
                for (int nt = 0; nt < 4; ++nt)
                    mma_f16(c[mt][nt], a[mt], b[nt]);
        }
        if (lane == 0) mbar_arrive(smem_base + EMPTY_OFF(cons_s));
        if (++cons_s == STAGES) { cons_s = 0; cons_ph ^= 1; }
    }

    // epilogue: ReLU + float2 stores (bias folded via K-extension)
    const int gr = lane >> 2;
    const int ct = lane & 3;
#pragma unroll
    for (int mt = 0; mt < 4; ++mt) {
#pragma unroll
        for (int nt = 0; nt < 4; ++nt) {
            int row = bm0 + wm * 64 + mt * 16 + gr;
            int o   = bn0 + wn * 32 + nt * 8 + ct * 2;
            size_t i0 = (size_t)row * N_DIM + o;
            float2 v0 = make_float2(fmaxf(c[mt][nt][0], 0.f), fmaxf(c[mt][nt][1], 0.f));
            float2 v1 = make_float2(fmaxf(c[mt][nt][2], 0.f), fmaxf(c[mt][nt][3], 0.f));
            *reinterpret_cast<float2*>(out + i0) = v0;
            *reinterpret_cast<float2*>(out + i0 + (size_t)8 * N_DIM) = v1;
        }
    }
}

// ---------------- launch -----------------------------------------------------
extern "C" void kernel_launch(void* const* d_in, const int* in_sizes, int n_in,
                              void* d_out, int out_size) {
    const float* x = nullptr;
    const float* cw = nullptr;
    const float* W = nullptr;
    const float* bias = nullptr;
    for (int i = 0; i < n_in; ++i) {
        switch (in_sizes[i]) {
            case M_DIM * I_DIM:         x    = (const float*)d_in[i]; break;
            case M_DIM * E_DIM:         cw   = (const float*)d_in[i]; break;
            case E_DIM * I_DIM * N_DIM: W    = (const float*)d_in[i]; break;
            case E_DIM * N_DIM:         bias = (const float*)d_in[i]; break;
            default: break;
        }
    }
    float* out = (float*)d_out;

    prep_w_kernel<<<2048, 256>>>(W);
    prep_a_kernel<<<4096, 256>>>(x, cw);
    prep_tail_kernel<<<(M_DIM * 64 + 64 * N_DIM + 255) / 256, 256>>>(cw, bias);

    cudaFuncSetAttribute(gemm_kernel, cudaFuncAttributeMaxDynamicSharedMemorySize,
                         SMEM_TOTAL);
    dim3 grid(N_DIM / BN, M_DIM / BM);  // (8, 32) = 256 CTAs, 1 wave @ occ 2
    gemm_kernel<<<grid, NTHREADS, SMEM_TOTAL>>>(out);
}